// round 15
// baseline (speedup 1.0000x reference)
#include <cuda_runtime.h>
#include <cuda_bf16.h>

#define NN  131072
#define CC  128
#define SS  6
#define BB  6
#define EE  131072
#define ELE 32768
#define GN_EPS 1e-5f

// ---------------- device scratch ----------------
static __device__ float g_bufA[(size_t)NN * CC];
static __device__ float g_bufB[(size_t)NN * CC];
static __device__ float g_temp[(size_t)NN * CC];
// split planes: [N][64] u32 (bf16x2 pairs), hi then lo
static __device__ unsigned g_fhi[(size_t)NN * 64];
static __device__ unsigned g_flo[(size_t)NN * 64];
// split weights: [96][hi 8192 | lo 8192] u32, layout [n=128][kp=64]
static __device__ unsigned g_wsp[(size_t)96 * 16384];

// ---------------- bf16 split helpers ----------------
__device__ __forceinline__ unsigned pack_bf2(__nv_bfloat16 lo16, __nv_bfloat16 hi16) {
    __nv_bfloat162 t(lo16, hi16);
    return *reinterpret_cast<unsigned*>(&t);
}
__device__ __forceinline__ void bsplit(float x, __nv_bfloat16& h, __nv_bfloat16& l) {
    h = __float2bfloat16(x);
    l = __float2bfloat16(x - __bfloat162float(h));
}
__device__ __forceinline__ void split2(float a, float b, unsigned& hi, unsigned& lo) {
    __nv_bfloat16 h0, l0, h1, l1;
    bsplit(a, h0, l0); bsplit(b, h1, l1);
    hi = pack_bf2(h0, h1);
    lo = pack_bf2(l0, l1);
}

__device__ __forceinline__ void mma16816(float acc[4],
                                         unsigned a0, unsigned a1, unsigned a2, unsigned a3,
                                         unsigned b0, unsigned b1) {
    asm volatile(
        "mma.sync.aligned.m16n8k16.row.col.f32.bf16.bf16.f32 "
        "{%0,%1,%2,%3}, {%4,%5,%6,%7}, {%8,%9}, {%0,%1,%2,%3};"
        : "+f"(acc[0]), "+f"(acc[1]), "+f"(acc[2]), "+f"(acc[3])
        : "r"(a0), "r"(a1), "r"(a2), "r"(a3), "r"(b0), "r"(b1));
}
__device__ __forceinline__ void ldsm_x4(unsigned& r0, unsigned& r1, unsigned& r2, unsigned& r3,
                                        unsigned addr) {
    asm volatile("ldmatrix.sync.aligned.m8n8.x4.shared.b16 {%0,%1,%2,%3}, [%4];"
                 : "=r"(r0), "=r"(r1), "=r"(r2), "=r"(r3) : "r"(addr));
}
__device__ __forceinline__ void cp16(unsigned dst_sh, const void* src) {
    asm volatile("cp.async.cg.shared.global [%0], [%1], 16;" :: "r"(dst_sh), "l"(src));
}
__device__ __forceinline__ void mbar_wait(unsigned addr, unsigned parity) {
    asm volatile(
        "{\n\t.reg .pred P1;\n\t"
        "WAIT_LOOP_%=:\n\t"
        "mbarrier.try_wait.parity.acquire.cta.shared::cta.b64 P1, [%0], %1, 0x989680;\n\t"
        "@P1 bra.uni WAIT_DONE_%=;\n\t"
        "bra.uni WAIT_LOOP_%=;\n\t"
        "WAIT_DONE_%=:\n\t}"
        :: "r"(addr), "r"(parity) : "memory");
}

// ---------------- weight pre-split kernel ----------------
__global__ void split_w_kernel(const float* __restrict__ ctr_w, const float* __restrict__ pre_w,
                               const float* __restrict__ suc_w, const float* __restrict__ left_w,
                               const float* __restrict__ right_w, const float* __restrict__ ctr2_w,
                               unsigned* __restrict__ out)
{
    const int m = blockIdx.x;
    const float* W;
    if (m < 6)       W = ctr_w   + (size_t)m        * 16384;
    else if (m < 42) W = pre_w   + (size_t)(m - 6)  * 16384;
    else if (m < 78) W = suc_w   + (size_t)(m - 42) * 16384;
    else if (m < 84) W = left_w  + (size_t)(m - 78) * 16384;
    else if (m < 90) W = right_w + (size_t)(m - 84) * 16384;
    else             W = ctr2_w  + (size_t)(m - 90) * 16384;
    unsigned* hi = out + (size_t)m * 16384;
    unsigned* lo = hi + 8192;
#pragma unroll
    for (int i = 0; i < 32; i++) {
        int p  = threadIdx.x + i * 256;
        int n  = p & 127;
        int kp = p >> 7;
        float w0 = W[(2 * kp) * CC + n];
        float w1 = W[(2 * kp + 1) * CC + n];
        unsigned h, l;
        split2(w0, w1, h, l);
        hi[n * 64 + kp] = h;
        lo[n * 64 + kp] = l;
    }
}

// ---------------- bulk-staged GEMM (round-13 proven shape) ----------------
// smem (u32):
//   sW    [0, 17408):      plane*8704 + n*68 + chunk*4
//   sA    [17408, 52224):  slot*17408 + plane*8704 + r*68 + chunk*4
//   sIdx  [52224, 52736):  slot*256 + {u:0-127, v:128-255}
//   mbar  [52736, 52740)
#define SMEM_U32 52740
#define SMEM_BYTES (SMEM_U32 * 4)

template <bool SCATTER>
__device__ __forceinline__ void stage_bulk(unsigned shb, int slot,
                                           const unsigned* __restrict__ Ahi,
                                           const unsigned* __restrict__ Alo,
                                           const int* sV, int row0, int tid, unsigned mbar)
{
    if (tid < 256) {
        int plane = tid >> 7;
        int r = tid & 127;
        int src = SCATTER ? sV[r] : (row0 + r);
        const void* srcp = (plane ? Alo : Ahi) + (size_t)src * 64;
        unsigned dst = shb + ((17408u + (unsigned)slot * 17408u +
                               (unsigned)plane * 8704u + (unsigned)r * 68u) << 2);
        asm volatile("mbarrier.arrive.expect_tx.shared.b64 _, [%0], %1;"
                     :: "r"(mbar), "r"(256u) : "memory");
        asm volatile(
            "cp.async.bulk.shared::cta.global.mbarrier::complete_tx::bytes [%0], [%1], %2, [%3];"
            :: "r"(dst), "l"(srcp), "r"(256u), "r"(mbar) : "memory");
    }
}

template <bool SCATTER>
__device__ __forceinline__ void gemm_body(unsigned* smem_u,
                                          const unsigned* __restrict__ Ahi,
                                          const unsigned* __restrict__ Alo,
                                          const unsigned* __restrict__ Wp,   // one matrix
                                          const int* __restrict__ u_idx,    // pre-offset
                                          const int* __restrict__ v_idx,
                                          float* __restrict__ out,
                                          int n_rows)
{
    int* sIdx = (int*)(smem_u + 52224);

    const int tid  = threadIdx.x;
    const int lane = tid & 31;
    const int wid  = tid >> 5;
    const int wr   = wid & 3;
    const int wc   = wid >> 2;
    const int tig  = lane & 3;
    const int gid  = lane >> 2;

    const int n_tiles = n_rows >> 7;
    int tile = blockIdx.x;
    if (tile >= n_tiles) return;

    const unsigned shb = (unsigned)__cvta_generic_to_shared((void*)smem_u);
    const unsigned mb0 = shb + 52736u * 4u;
    const unsigned mb1 = mb0 + 8u;

    if (tid == 0) {
        asm volatile("mbarrier.init.shared.b64 [%0], %1;" :: "r"(mb0), "r"(256u) : "memory");
        asm volatile("mbarrier.init.shared.b64 [%0], %1;" :: "r"(mb1), "r"(256u) : "memory");
    }
    __syncthreads();

    {
        const uint4* wg = (const uint4*)Wp;
#pragma unroll
        for (int j = 0; j < 8; j++) {
            int fi = tid + j * 512;
            int plane = fi >> 11;
            int p = fi & 2047;
            int n = p >> 4;
            int c = p & 15;
            unsigned dst = shb + (((unsigned)plane * 8704u + (unsigned)n * 68u +
                                   (unsigned)c * 4u) << 2);
            cp16(dst, wg + fi);
        }
        asm volatile("cp.async.commit_group;" ::: "memory");
    }

    if (SCATTER && tid < 256) {
        const int* src = (tid < 128) ? u_idx : v_idx;
        sIdx[tid] = src[(tile << 7) + (tid & 127)];
    }
    __syncthreads();
    stage_bulk<SCATTER>(shb, 0, Ahi, Alo, sIdx + 128, tile << 7, tid, mb0);

    asm volatile("cp.async.wait_group 0;" ::: "memory");
    __syncthreads();

    const int hi4A = lane >> 4;
    const int hi4B = (lane & 8) >> 3;
    unsigned baseA[2];
#pragma unroll
    for (int rt = 0; rt < 2; rt++) {
        int rr = wr * 32 + rt * 16 + (lane & 15);
        baseA[rt] = shb + ((17408u + (unsigned)rr * 68u) << 2);
    }
    unsigned bBase[2][2];
#pragma unroll
    for (int nt2 = 0; nt2 < 2; nt2++) {
        int nn = wc * 32 + nt2 * 16 + (lane & 7) + ((lane & 16) >> 1);
#pragma unroll
        for (int pl = 0; pl < 2; pl++)
            bBase[nt2][pl] = shb + (((unsigned)pl * 8704u + (unsigned)nn * 68u) << 2);
    }

    int slot = 0;
    unsigned ph0 = 0, ph1 = 0;
#pragma unroll 1
    while (true) {
        const int row0 = tile << 7;
        const int next = tile + gridDim.x;
        const bool has_next = (next < n_tiles);

        int nreg = 0;
        if (SCATTER && has_next && tid < 256) {
            const int* src = (tid < 128) ? u_idx : v_idx;
            nreg = src[(next << 7) + (tid & 127)];
        }

        if (slot == 0) { mbar_wait(mb0, ph0); ph0 ^= 1; }
        else           { mbar_wait(mb1, ph1); ph1 ^= 1; }

        if (SCATTER && has_next && tid < 256)
            sIdx[(slot ^ 1) * 256 + tid] = nreg;
        __syncthreads();

        if (has_next)
            stage_bulk<SCATTER>(shb, slot ^ 1, Ahi, Alo, sIdx + (slot ^ 1) * 256 + 128,
                                next << 7, tid, slot ? mb0 : mb1);

        const unsigned slotb = (unsigned)slot * 69632u;
        float acc[2][4][4];
#pragma unroll
        for (int rt = 0; rt < 2; rt++)
#pragma unroll
            for (int nt = 0; nt < 4; nt++)
#pragma unroll
                for (int q = 0; q < 4; q++) acc[rt][nt][q] = 0.f;

#pragma unroll
        for (int ks = 0; ks < 8; ks++) {
            unsigned ah[2][4], al[2][4];
#pragma unroll
            for (int rt = 0; rt < 2; rt++) {
                unsigned ch = (unsigned)((2 * ks + hi4A) << 4);
                ldsm_x4(ah[rt][0], ah[rt][1], ah[rt][2], ah[rt][3],
                        baseA[rt] + slotb + ch);
                ldsm_x4(al[rt][0], al[rt][1], al[rt][2], al[rt][3],
                        baseA[rt] + slotb + 34816u + ch);
            }
#pragma unroll
            for (int nt2 = 0; nt2 < 2; nt2++) {
                unsigned bh[4], bl[4];
                unsigned ch = (unsigned)((2 * ks + hi4B) << 4);
                ldsm_x4(bh[0], bh[1], bh[2], bh[3], bBase[nt2][0] + ch);
                ldsm_x4(bl[0], bl[1], bl[2], bl[3], bBase[nt2][1] + ch);
#pragma unroll
                for (int half = 0; half < 2; half++) {
                    const int nt = nt2 * 2 + half;
                    unsigned b0h = bh[2 * half], b1h = bh[2 * half + 1];
                    unsigned b0l = bl[2 * half], b1l = bl[2 * half + 1];
#pragma unroll
                    for (int rt = 0; rt < 2; rt++) {
                        mma16816(acc[rt][nt], ah[rt][0], ah[rt][1], ah[rt][2], ah[rt][3], b0h, b1h);
                        mma16816(acc[rt][nt], ah[rt][0], ah[rt][1], ah[rt][2], ah[rt][3], b0l, b1l);
                        mma16816(acc[rt][nt], al[rt][0], al[rt][1], al[rt][2], al[rt][3], b0h, b1h);
                    }
                }
            }
        }

        const bool even = (tig & 1) == 0;
        const int colofs = (tig & 2) ? 4 : 0;
#pragma unroll
        for (int rt = 0; rt < 2; rt++) {
            const int arow = wr * 32 + rt * 16 + gid + (even ? 0 : 8);
            float* base;
            if (SCATTER) base = out + (size_t)sIdx[slot * 256 + arow] * CC;
            else         base = out + (size_t)(row0 + arow) * CC;
#pragma unroll
            for (int nt = 0; nt < 4; nt++) {
                float c0 = acc[rt][nt][0], c1 = acc[rt][nt][1];
                float c2 = acc[rt][nt][2], c3 = acc[rt][nt][3];
                float e0 = __shfl_xor_sync(0xffffffffu, c0, 1);
                float e1 = __shfl_xor_sync(0xffffffffu, c1, 1);
                float e2 = __shfl_xor_sync(0xffffffffu, c2, 1);
                float e3 = __shfl_xor_sync(0xffffffffu, c3, 1);
                float x0, x1, x2, x3;
                if (even) { x0 = c0; x1 = c1; x2 = e0; x3 = e1; }
                else      { x0 = e2; x1 = e3; x2 = c2; x3 = c3; }
                float* p = base + wc * 32 + nt * 8 + colofs;
                if (SCATTER) {
                    asm volatile("red.global.add.v4.f32 [%0], {%1,%2,%3,%4};"
                                 :: "l"(p), "f"(x0), "f"(x1), "f"(x2), "f"(x3) : "memory");
                } else {
                    float4 v; v.x = x0; v.y = x1; v.z = x2; v.w = x3;
                    *(float4*)p = v;
                }
            }
        }

        if (!has_next) break;
        if (SCATTER) __syncthreads();
        tile = next;
        slot ^= 1;
    }
}

// ---------------- dense GEMM kernel ----------------
__global__ void __launch_bounds__(512, 1)
msg_dense_kernel(const unsigned* __restrict__ Ahi, const unsigned* __restrict__ Alo,
                 const unsigned* __restrict__ Wp, float* __restrict__ out, int n_rows)
{
    extern __shared__ unsigned smem_u[];
    gemm_body<false>(smem_u, Ahi, Alo, Wp, nullptr, nullptr, out, n_rows);
}

// ---------------- merged scatter kernel: two homogeneous edge groups ----------------
// y < half_y -> group 1 slice y; else group 2 slice (y-half_y). Same n_rows both groups.
__global__ void __launch_bounds__(512, 1)
msg_scatter_kernel(const unsigned* __restrict__ Ahi, const unsigned* __restrict__ Alo,
                   const unsigned* __restrict__ Wbase, long wofs2,
                   const int* __restrict__ u1, const int* __restrict__ v1,
                   const int* __restrict__ u2, const int* __restrict__ v2,
                   int half_y, float* __restrict__ out, int n_rows)
{
    extern __shared__ unsigned smem_u[];
    const int y = blockIdx.y;
    const unsigned* Wp;
    const int* uu;
    const int* vv;
    if (y < half_y) {
        Wp = Wbase + (size_t)y * 16384;
        uu = u1 + (size_t)y * n_rows;
        vv = v1 + (size_t)y * n_rows;
    } else {
        int y2 = y - half_y;
        Wp = Wbase + wofs2 + (size_t)y2 * 16384;
        uu = u2 + (size_t)y2 * n_rows;
        vv = v2 + (size_t)y2 * n_rows;
    }
    gemm_body<true>(smem_u, Ahi, Alo, Wp, uu, vv, out, n_rows);
}

// ---------------- fully fused: GN1+relu -> GEMM -> GN2 + residual + relu + split ----------------
// smem (u32):
//   sW    [0, 17408)
//   sAf32 [17408, 34304):  r*132 stride, 128 floats/row
//   sAbf  [34304, 51712):  hi 8704 | lo 8704, r*68 stride
//   sGNS  [51712, 52224)   sGNQ [52224, 52736)
//   sG1   [52736, 52864)   sB1 [52864, 52992)  sG2 [52992, 53120)  sB2 [53120, 53248)
//   mbar  [53248, 53250)
#define SMEM2_U32 53252
#define SMEM2_BYTES (SMEM2_U32 * 4)

__global__ void __launch_bounds__(512, 1)
norm_gemm_gn_res_kernel(const float* __restrict__ temp,
                        const unsigned* __restrict__ Wp,
                        const float* __restrict__ g1, const float* __restrict__ b1,
                        const float* __restrict__ g2, const float* __restrict__ b2,
                        const float* __restrict__ iden,
                        float* __restrict__ outp,
                        unsigned* __restrict__ ohi, unsigned* __restrict__ olo,
                        int n_rows)
{
    extern __shared__ unsigned smem_u[];
    float* sGNS = (float*)(smem_u + 51712);
    float* sGNQ = (float*)(smem_u + 52224);
    float* sG1  = (float*)(smem_u + 52736);
    float* sB1  = (float*)(smem_u + 52864);
    float* sG2  = (float*)(smem_u + 52992);
    float* sB2  = (float*)(smem_u + 53120);

    const int tid  = threadIdx.x;
    const int lane = tid & 31;
    const int wid  = tid >> 5;
    const int wr   = wid & 3;
    const int wc   = wid >> 2;
    const int tig  = lane & 3;
    const int gid  = lane >> 2;

    const int n_tiles = n_rows >> 7;
    int tile = blockIdx.x;
    if (tile >= n_tiles) return;

    const unsigned shb = (unsigned)__cvta_generic_to_shared((void*)smem_u);
    const unsigned mb = shb + 53248u * 4u;

    if (tid == 0)
        asm volatile("mbarrier.init.shared.b64 [%0], %1;" :: "r"(mb), "r"(128u) : "memory");
    if (tid < 128)      sG1[tid]       = g1[tid];
    else if (tid < 256) sB1[tid - 128] = b1[tid - 128];
    else if (tid < 384) sG2[tid - 256] = g2[tid - 256];
    else                sB2[tid - 384] = b2[tid - 384];
    __syncthreads();

    // stage W
    {
        const uint4* wg = (const uint4*)Wp;
#pragma unroll
        for (int j = 0; j < 8; j++) {
            int fi = tid + j * 512;
            int plane = fi >> 11;
            int p = fi & 2047;
            int n = p >> 4;
            int c = p & 15;
            unsigned dst = shb + (((unsigned)plane * 8704u + (unsigned)n * 68u +
                                   (unsigned)c * 4u) << 2);
            cp16(dst, wg + fi);
        }
        asm volatile("cp.async.commit_group;" ::: "memory");
    }

    auto stage_f32 = [&](int row0) {
        if (tid < 128) {
            const void* srcp = temp + (size_t)(row0 + tid) * CC;
            unsigned dst = shb + ((17408u + (unsigned)tid * 132u) << 2);
            asm volatile("mbarrier.arrive.expect_tx.shared.b64 _, [%0], %1;"
                         :: "r"(mb), "r"(512u) : "memory");
            asm volatile(
                "cp.async.bulk.shared::cta.global.mbarrier::complete_tx::bytes [%0], [%1], %2, [%3];"
                :: "r"(dst), "l"(srcp), "r"(512u), "r"(mb) : "memory");
        }
    };
    stage_f32(tile << 7);
    asm volatile("cp.async.wait_group 0;" ::: "memory");   // W resident
    __syncthreads();

    const int hi4A = lane >> 4;
    const int hi4B = (lane & 8) >> 3;
    unsigned baseA[2];
#pragma unroll
    for (int rt = 0; rt < 2; rt++) {
        int rr = wr * 32 + rt * 16 + (lane & 15);
        baseA[rt] = shb + ((34304u + (unsigned)rr * 68u) << 2);
    }
    unsigned bBase[2][2];
#pragma unroll
    for (int nt2 = 0; nt2 < 2; nt2++) {
        int nn = wc * 32 + nt2 * 16 + (lane & 7) + ((lane & 16) >> 1);
#pragma unroll
        for (int pl = 0; pl < 2; pl++)
            bBase[nt2][pl] = shb + (((unsigned)pl * 8704u + (unsigned)nn * 68u) << 2);
    }
    const bool even = (tig & 1) == 0;
    const int colofs = (tig & 2) ? 4 : 0;
    const int erow0 = wr * 32 + gid + (even ? 0 : 8);

    const int cr  = tid >> 2;
    const int cs  = tid & 3;
    float* crow = (float*)(smem_u + 17408) + cr * 132 + cs * 32;
    unsigned* hrow = smem_u + 34304 + cr * 68 + cs * 16;
    unsigned* lrow = hrow + 8704;

    unsigned ph = 0;
#pragma unroll 1
    while (true) {
        const int row0 = tile << 7;
        const int next = tile + gridDim.x;
        const bool has_next = (next < n_tiles);

        mbar_wait(mb, ph); ph ^= 1;

        // ---- GN1 + relu + split -> bf16 planes ----
        {
            float y[32];
#pragma unroll
            for (int j = 0; j < 8; j++) {
                float4 v = *(const float4*)(crow + j * 4);
                y[4 * j] = v.x; y[4 * j + 1] = v.y; y[4 * j + 2] = v.z; y[4 * j + 3] = v.w;
            }
            float s = 0.f, q = 0.f;
#pragma unroll
            for (int j = 0; j < 32; j++) { s += y[j]; q += y[j] * y[j]; }
            s += __shfl_xor_sync(0xffffffffu, s, 1);
            q += __shfl_xor_sync(0xffffffffu, q, 1);
            s += __shfl_xor_sync(0xffffffffu, s, 2);
            q += __shfl_xor_sync(0xffffffffu, q, 2);
            float mu = s * (1.f / CC);
            float var = q * (1.f / CC) - mu * mu;
            float rs = rsqrtf(var + GN_EPS);
            const float* gg = sG1 + cs * 32;
            const float* bb = sB1 + cs * 32;
            unsigned hv[16], lv[16];
#pragma unroll
            for (int j = 0; j < 16; j++) {
                float h0 = fmaxf(fmaf((y[2 * j] - mu) * rs, gg[2 * j], bb[2 * j]), 0.f);
                float h1 = fmaxf(fmaf((y[2 * j + 1] - mu) * rs, gg[2 * j + 1], bb[2 * j + 1]), 0.f);
                split2(h0, h1, hv[j], lv[j]);
            }
#pragma unroll
            for (int j = 0; j < 4; j++) {
                *(uint4*)(hrow + j * 4) = *(uint4*)(hv + j * 4);
                *(uint4*)(lrow + j * 4) = *(uint4*)(lv + j * 4);
            }
        }
        __syncthreads();   // bf16 planes ready; f32 buffer free

        if (has_next) stage_f32(next << 7);

        // ---- MMA ----
        float acc[2][4][4];
#pragma unroll
        for (int rt = 0; rt < 2; rt++)
#pragma unroll
            for (int nt = 0; nt < 4; nt++)
#pragma unroll
                for (int q2 = 0; q2 < 4; q2++) acc[rt][nt][q2] = 0.f;

#pragma unroll
        for (int ks = 0; ks < 8; ks++) {
            unsigned ah[2][4], al[2][4];
#pragma unroll
            for (int rt = 0; rt < 2; rt++) {
                unsigned ch = (unsigned)((2 * ks + hi4A) << 4);
                ldsm_x4(ah[rt][0], ah[rt][1], ah[rt][2], ah[rt][3], baseA[rt] + ch);
                ldsm_x4(al[rt][0], al[rt][1], al[rt][2], al[rt][3], baseA[rt] + 34816u + ch);
            }
#pragma unroll
            for (int nt2 = 0; nt2 < 2; nt2++) {
                unsigned bh[4], bl[4];
                unsigned ch = (unsigned)((2 * ks + hi4B) << 4);
                ldsm_x4(bh[0], bh[1], bh[2], bh[3], bBase[nt2][0] + ch);
                ldsm_x4(bl[0], bl[1], bl[2], bl[3], bBase[nt2][1] + ch);
#pragma unroll
                for (int half = 0; half < 2; half++) {
                    const int nt = nt2 * 2 + half;
                    unsigned b0h = bh[2 * half], b1h = bh[2 * half + 1];
                    unsigned b0l = bl[2 * half], b1l = bl[2 * half + 1];
#pragma unroll
                    for (int rt = 0; rt < 2; rt++) {
                        mma16816(acc[rt][nt], ah[rt][0], ah[rt][1], ah[rt][2], ah[rt][3], b0h, b1h);
                        mma16816(acc[rt][nt], ah[rt][0], ah[rt][1], ah[rt][2], ah[rt][3], b0l, b1l);
                        mma16816(acc[rt][nt], al[rt][0], al[rt][1], al[rt][2], al[rt][3], b0h, b1h);
                    }
                }
            }
        }

        // ---- GN2 + residual + relu epilogue ----
        float sP[2] = {0.f, 0.f}, sQ[2] = {0.f, 0.f};
#pragma unroll
        for (int rt = 0; rt < 2; rt++) {
#pragma unroll
            for (int nt = 0; nt < 4; nt++) {
                float c0 = acc[rt][nt][0], c1 = acc[rt][nt][1];
                float c2 = acc[rt][nt][2], c3 = acc[rt][nt][3];
                float e0 = __shfl_xor_sync(0xffffffffu, c0, 1);
                float e1 = __shfl_xor_sync(0xffffffffu, c1, 1);
                float e2 = __shfl_xor_sync(0xffffffffu, c2, 1);
                float e3 = __shfl_xor_sync(0xffffffffu, c3, 1);
                float x0, x1, x2, x3;
                if (even) { x0 = c0; x1 = c1; x2 = e0; x3 = e1; }
                else      { x0 = e2; x1 = e3; x2 = c2; x3 = c3; }
                acc[rt][nt][0] = x0; acc[rt][nt][1] = x1;
                acc[rt][nt][2] = x2; acc[rt][nt][3] = x3;
                sP[rt] += x0 + x1 + x2 + x3;
                sQ[rt] += x0 * x0 + x1 * x1 + x2 * x2 + x3 * x3;
            }
            sP[rt] += __shfl_xor_sync(0xffffffffu, sP[rt], 2);
            sQ[rt] += __shfl_xor_sync(0xffffffffu, sQ[rt], 2);
        }
        if (tig < 2) {
            int rw = wr * 32 + gid + (tig & 1) * 8;
#pragma unroll
            for (int rt = 0; rt < 2; rt++) {
                sGNS[(rw + rt * 16) * 4 + wc] = sP[rt];
                sGNQ[(rw + rt * 16) * 4 + wc] = sQ[rt];
            }
        }
        __syncthreads();

#pragma unroll
        for (int rt = 0; rt < 2; rt++) {
            const int row = erow0 + rt * 16;
            float s4 = sGNS[row * 4] + sGNS[row * 4 + 1] + sGNS[row * 4 + 2] + sGNS[row * 4 + 3];
            float q4 = sGNQ[row * 4] + sGNQ[row * 4 + 1] + sGNQ[row * 4 + 2] + sGNQ[row * 4 + 3];
            float mu  = s4 * (1.f / CC);
            float var = q4 * (1.f / CC) - mu * mu;
            float rs  = rsqrtf(var + GN_EPS);
            const size_t grow = (size_t)(row0 + row);
            const float* idrow = iden + grow * CC;
            float* orow = outp + grow * CC;
#pragma unroll
            for (int nt = 0; nt < 4; nt++) {
                const int col0 = wc * 32 + nt * 8 + colofs;
                float4 gg = *(const float4*)(sG2 + col0);
                float4 bb = *(const float4*)(sB2 + col0);
                float4 id4 = *(const float4*)(idrow + col0);
                float y0 = fmaxf(fmaf((acc[rt][nt][0] - mu) * rs, gg.x, bb.x) + id4.x, 0.f);
                float y1 = fmaxf(fmaf((acc[rt][nt][1] - mu) * rs, gg.y, bb.y) + id4.y, 0.f);
                float y2 = fmaxf(fmaf((acc[rt][nt][2] - mu) * rs, gg.z, bb.z) + id4.z, 0.f);
                float y3 = fmaxf(fmaf((acc[rt][nt][3] - mu) * rs, gg.w, bb.w) + id4.w, 0.f);
                float4 o4; o4.x = y0; o4.y = y1; o4.z = y2; o4.w = y3;
                *(float4*)(orow + col0) = o4;
                unsigned h0, l0, h1, l1;
                split2(y0, y1, h0, l0);
                split2(y2, y3, h1, l1);
                uint2 hv; hv.x = h0; hv.y = h1;
                uint2 lv; lv.x = l0; lv.y = l1;
                *(uint2*)(ohi + grow * 64 + (col0 >> 1)) = hv;
                *(uint2*)(olo + grow * 64 + (col0 >> 1)) = lv;
            }
        }
        __syncthreads();   // GNS/GNQ + bf16 planes free for next tile

        if (!has_next) break;
        tile = next;
    }
}

// ---------------- input encoder (+ split write) ----------------
__global__ void encoder_kernel(const float* __restrict__ ctrs, const float* __restrict__ feats,
                               const float* __restrict__ icw0, const float* __restrict__ icb0,
                               const float* __restrict__ icw1, const float* __restrict__ icg,
                               const float* __restrict__ icbt,
                               const float* __restrict__ ifw0, const float* __restrict__ ifb0,
                               const float* __restrict__ ifw1, const float* __restrict__ ifg,
                               const float* __restrict__ ifbt,
                               float* __restrict__ out,
                               unsigned* __restrict__ ohi, unsigned* __restrict__ olo)
{
    const int tid = threadIdx.x;
    const int r = tid >> 7;
    const int c = tid & 127;
    const int row = (blockIdx.x << 1) + r;
    const int warp = (tid >> 5) & 3;
    const int lane = tid & 31;
    __shared__ float sh[2][CC];
    __shared__ float sred[2][2][4];

    float ysum = 0.f;
#pragma unroll
    for (int br = 0; br < 2; br++) {
        const float* x  = br ? feats : ctrs;
        const float* w0 = br ? ifw0 : icw0;
        const float* b0 = br ? ifb0 : icb0;
        const float* w1 = br ? ifw1 : icw1;
        const float* g  = br ? ifg  : icg;
        const float* bt = br ? ifbt : icbt;
        const float x0 = x[row * 2 + 0];
        const float x1 = x[row * 2 + 1];
        float h = fmaxf(fmaf(x1, w0[CC + c], fmaf(x0, w0[c], b0[c])), 0.f);
        __syncthreads();
        sh[r][c] = h;
        __syncthreads();
        float z = 0.f;
#pragma unroll 8
        for (int k = 0; k < CC; k++) z = fmaf(sh[r][k], w1[k * CC + c], z);
        float s = z, sq = z * z;
#pragma unroll
        for (int o = 16; o > 0; o >>= 1) {
            s  += __shfl_xor_sync(0xffffffffu, s, o);
            sq += __shfl_xor_sync(0xffffffffu, sq, o);
        }
        if (lane == 0) { sred[r][0][warp] = s; sred[r][1][warp] = sq; }
        __syncthreads();
        float mu  = (sred[r][0][0] + sred[r][0][1] + sred[r][0][2] + sred[r][0][3]) * (1.f / CC);
        float ms  = (sred[r][1][0] + sred[r][1][1] + sred[r][1][2] + sred[r][1][3]) * (1.f / CC);
        float var = ms - mu * mu;
        ysum += (z - mu) * rsqrtf(var + GN_EPS) * g[c] + bt[c];
    }
    float y = fmaxf(ysum, 0.f);
    out[(size_t)row * CC + c] = y;
    float yn = __shfl_down_sync(0xffffffffu, y, 1);
    if ((c & 1) == 0) {
        unsigned h, l; split2(y, yn, h, l);
        ohi[(size_t)row * 64 + (c >> 1)] = h;
        olo[(size_t)row * 64 + (c >> 1)] = l;
    }
}

extern "C" void kernel_launch(void* const* d_in, const int* in_sizes, int n_in,
                              void* d_out, int out_size)
{
    const float* ctrs    = (const float*)d_in[0];
    const float* feats   = (const float*)d_in[1];
    const int*   pre_u   = (const int*)d_in[2];
    const int*   pre_v   = (const int*)d_in[3];
    const int*   suc_u   = (const int*)d_in[4];
    const int*   suc_v   = (const int*)d_in[5];
    const int*   left_u  = (const int*)d_in[6];
    const int*   left_v  = (const int*)d_in[7];
    const int*   right_u = (const int*)d_in[8];
    const int*   right_v = (const int*)d_in[9];
    const float* ic_w0   = (const float*)d_in[10];
    const float* ic_b0   = (const float*)d_in[11];
    const float* ic_w1   = (const float*)d_in[12];
    const float* ic_g    = (const float*)d_in[13];
    const float* ic_bt   = (const float*)d_in[14];
    const float* if_w0   = (const float*)d_in[15];
    const float* if_b0   = (const float*)d_in[16];
    const float* if_w1   = (const float*)d_in[17];
    const float* if_g    = (const float*)d_in[18];
    const float* if_bt   = (const float*)d_in[19];
    const float* ctr_w   = (const float*)d_in[20];
    const float* pre_w   = (const float*)d_in[21];
    const float* suc_w   = (const float*)d_in[22];
    const float* left_w  = (const float*)d_in[23];
    const float* right_w = (const float*)d_in[24];
    const float* norm_g  = (const float*)d_in[25];
    const float* norm_b  = (const float*)d_in[26];
    const float* ctr2_w  = (const float*)d_in[27];
    const float* ctr2_g  = (const float*)d_in[28];
    const float* ctr2_b  = (const float*)d_in[29];

    float *bufA, *bufB, *temp;
    unsigned *fhi, *flo, *wsp;
    cudaGetSymbolAddress((void**)&bufA, g_bufA);
    cudaGetSymbolAddress((void**)&bufB, g_bufB);
    cudaGetSymbolAddress((void**)&temp, g_temp);
    cudaGetSymbolAddress((void**)&fhi, g_fhi);
    cudaGetSymbolAddress((void**)&flo, g_flo);
    cudaGetSymbolAddress((void**)&wsp, g_wsp);

    cudaFuncSetAttribute(msg_dense_kernel,   cudaFuncAttributeMaxDynamicSharedMemorySize, SMEM_BYTES);
    cudaFuncSetAttribute(msg_scatter_kernel, cudaFuncAttributeMaxDynamicSharedMemorySize, SMEM_BYTES);
    cudaFuncSetAttribute(norm_gemm_gn_res_kernel, cudaFuncAttributeMaxDynamicSharedMemorySize, SMEM2_BYTES);

    // one-time weight split (96 matrices)
    split_w_kernel<<<96, 256>>>(ctr_w, pre_w, suc_w, left_w, right_w, ctr2_w, wsp);

    // initial feat -> bufA (f32) + split planes
    encoder_kernel<<<NN / 2, 256>>>(ctrs, feats,
                                    ic_w0, ic_b0, ic_w1, ic_g, ic_bt,
                                    if_w0, if_b0, if_w1, if_g, if_bt,
                                    bufA, fhi, flo);

    float* fin = bufA;
    for (int i = 0; i < BB; i++) {
        // temp = feat @ ctr_w[i]
        msg_dense_kernel<<<148, 512, SMEM_BYTES>>>(
            fhi, flo, wsp + (size_t)i * 16384, temp, NN);
        // merged pre+suc scatter (12 homogeneous EE slices)
        msg_scatter_kernel<<<dim3(74, 2 * SS), 512, SMEM_BYTES>>>(
            fhi, flo, wsp + (size_t)(6 + i * 6) * 16384, (long)36 * 16384,
            pre_u, pre_v, suc_u, suc_v, SS, temp, EE);
        // merged left+right scatter (2 homogeneous ELE slices)
        msg_scatter_kernel<<<dim3(148, 2), 512, SMEM_BYTES>>>(
            fhi, flo, wsp + (size_t)(78 + i) * 16384, (long)6 * 16384,
            left_u, left_v, right_u, right_v, 1, temp, ELE);
        // feat = relu(GN2(relu(GN1(temp)) @ ctr2_w[i]) + identity) -- fully fused
        float* dst = (i == BB - 1) ? (float*)d_out : ((fin == bufA) ? bufB : bufA);
        norm_gemm_gn_res_kernel<<<148, 512, SMEM2_BYTES>>>(
            temp, wsp + (size_t)(90 + i) * 16384,
            norm_g + i * CC, norm_b + i * CC, ctr2_g + i * CC, ctr2_b + i * CC,
            fin, dst, fhi, flo, NN);
        fin = dst;
    }
}

// round 16
// speedup vs baseline: 1.0933x; 1.0933x over previous
#include <cuda_runtime.h>
#include <cuda_bf16.h>

#define NN  131072
#define CC  128
#define SS  6
#define BB  6
#define EE  131072
#define ELE 32768
#define GN_EPS 1e-5f

// ---------------- device scratch ----------------
static __device__ float g_temp[(size_t)NN * CC];
// split planes: [N][64] u32 (bf16x2 pairs), hi then lo
static __device__ unsigned g_fhi[(size_t)NN * 64];
static __device__ unsigned g_flo[(size_t)NN * 64];
// split weights: [96][hi 8192 | lo 8192] u32, layout [n=128][kp=64]
static __device__ unsigned g_wsp[(size_t)96 * 16384];

// ---------------- bf16 split helpers ----------------
__device__ __forceinline__ unsigned pack_bf2(__nv_bfloat16 lo16, __nv_bfloat16 hi16) {
    __nv_bfloat162 t(lo16, hi16);
    return *reinterpret_cast<unsigned*>(&t);
}
__device__ __forceinline__ void bsplit(float x, __nv_bfloat16& h, __nv_bfloat16& l) {
    h = __float2bfloat16(x);
    l = __float2bfloat16(x - __bfloat162float(h));
}
__device__ __forceinline__ void split2(float a, float b, unsigned& hi, unsigned& lo) {
    __nv_bfloat16 h0, l0, h1, l1;
    bsplit(a, h0, l0); bsplit(b, h1, l1);
    hi = pack_bf2(h0, h1);
    lo = pack_bf2(l0, l1);
}

__device__ __forceinline__ void mma16816(float acc[4],
                                         unsigned a0, unsigned a1, unsigned a2, unsigned a3,
                                         unsigned b0, unsigned b1) {
    asm volatile(
        "mma.sync.aligned.m16n8k16.row.col.f32.bf16.bf16.f32 "
        "{%0,%1,%2,%3}, {%4,%5,%6,%7}, {%8,%9}, {%0,%1,%2,%3};"
        : "+f"(acc[0]), "+f"(acc[1]), "+f"(acc[2]), "+f"(acc[3])
        : "r"(a0), "r"(a1), "r"(a2), "r"(a3), "r"(b0), "r"(b1));
}
__device__ __forceinline__ void ldsm_x4(unsigned& r0, unsigned& r1, unsigned& r2, unsigned& r3,
                                        unsigned addr) {
    asm volatile("ldmatrix.sync.aligned.m8n8.x4.shared.b16 {%0,%1,%2,%3}, [%4];"
                 : "=r"(r0), "=r"(r1), "=r"(r2), "=r"(r3) : "r"(addr));
}
__device__ __forceinline__ void cp16(unsigned dst_sh, const void* src) {
    asm volatile("cp.async.cg.shared.global [%0], [%1], 16;" :: "r"(dst_sh), "l"(src));
}
__device__ __forceinline__ void mbar_wait(unsigned addr, unsigned parity) {
    asm volatile(
        "{\n\t.reg .pred P1;\n\t"
        "WAIT_LOOP_%=:\n\t"
        "mbarrier.try_wait.parity.acquire.cta.shared::cta.b64 P1, [%0], %1, 0x989680;\n\t"
        "@P1 bra.uni WAIT_DONE_%=;\n\t"
        "bra.uni WAIT_LOOP_%=;\n\t"
        "WAIT_DONE_%=:\n\t}"
        :: "r"(addr), "r"(parity) : "memory");
}

// ---------------- weight pre-split kernel ----------------
__global__ void split_w_kernel(const float* __restrict__ ctr_w, const float* __restrict__ pre_w,
                               const float* __restrict__ suc_w, const float* __restrict__ left_w,
                               const float* __restrict__ right_w, const float* __restrict__ ctr2_w,
                               unsigned* __restrict__ out)
{
    const int m = blockIdx.x;
    const float* W;
    if (m < 6)       W = ctr_w   + (size_t)m        * 16384;
    else if (m < 42) W = pre_w   + (size_t)(m - 6)  * 16384;
    else if (m < 78) W = suc_w   + (size_t)(m - 42) * 16384;
    else if (m < 84) W = left_w  + (size_t)(m - 78) * 16384;
    else if (m < 90) W = right_w + (size_t)(m - 84) * 16384;
    else             W = ctr2_w  + (size_t)(m - 90) * 16384;
    unsigned* hi = out + (size_t)m * 16384;
    unsigned* lo = hi + 8192;
#pragma unroll
    for (int i = 0; i < 32; i++) {
        int p  = threadIdx.x + i * 256;
        int n  = p & 127;
        int kp = p >> 7;
        float w0 = W[(2 * kp) * CC + n];
        float w1 = W[(2 * kp + 1) * CC + n];
        unsigned h, l;
        split2(w0, w1, h, l);
        hi[n * 64 + kp] = h;
        lo[n * 64 + kp] = l;
    }
}

// ---------------- bulk-staged GEMM (round-13 proven shape, untouched) ----------------
// smem (u32):
//   sW    [0, 17408):      plane*8704 + n*68 + chunk*4
//   sA    [17408, 52224):  slot*17408 + plane*8704 + r*68 + chunk*4
//   sIdx  [52224, 52736):  slot*256 + {u:0-127, v:128-255}
//   mbar  [52736, 52740)
#define SMEM_U32 52740
#define SMEM_BYTES (SMEM_U32 * 4)

template <bool SCATTER>
__device__ __forceinline__ void stage_bulk(unsigned shb, int slot,
                                           const unsigned* __restrict__ Ahi,
                                           const unsigned* __restrict__ Alo,
                                           const int* sV, int row0, int tid, unsigned mbar)
{
    if (tid < 256) {
        int plane = tid >> 7;
        int r = tid & 127;
        int src = SCATTER ? sV[r] : (row0 + r);
        const void* srcp = (plane ? Alo : Ahi) + (size_t)src * 64;
        unsigned dst = shb + ((17408u + (unsigned)slot * 17408u +
                               (unsigned)plane * 8704u + (unsigned)r * 68u) << 2);
        asm volatile("mbarrier.arrive.expect_tx.shared.b64 _, [%0], %1;"
                     :: "r"(mbar), "r"(256u) : "memory");
        asm volatile(
            "cp.async.bulk.shared::cta.global.mbarrier::complete_tx::bytes [%0], [%1], %2, [%3];"
            :: "r"(dst), "l"(srcp), "r"(256u), "r"(mbar) : "memory");
    }
}

template <bool SCATTER>
__global__ void __launch_bounds__(512, 1)
msg_mma_kernel(const unsigned* __restrict__ Ahi,
               const unsigned* __restrict__ Alo,
               const unsigned* __restrict__ Wsp,   // + blockIdx.y*16384
               const int* __restrict__ u_idx,      // + blockIdx.y*n_rows
               const int* __restrict__ v_idx,
               float* __restrict__ out,
               int n_rows)
{
    extern __shared__ unsigned smem_u[];
    int* sIdx = (int*)(smem_u + 52224);

    const int tid  = threadIdx.x;
    const int lane = tid & 31;
    const int wid  = tid >> 5;
    const int wr   = wid & 3;
    const int wc   = wid >> 2;
    const int tig  = lane & 3;
    const int gid  = lane >> 2;

    const int n_tiles = n_rows >> 7;
    int tile = blockIdx.x;
    if (tile >= n_tiles) return;

    const unsigned shb = (unsigned)__cvta_generic_to_shared((void*)smem_u);
    const unsigned mb0 = shb + 52736u * 4u;
    const unsigned mb1 = mb0 + 8u;

    if (tid == 0) {
        asm volatile("mbarrier.init.shared.b64 [%0], %1;" :: "r"(mb0), "r"(256u) : "memory");
        asm volatile("mbarrier.init.shared.b64 [%0], %1;" :: "r"(mb1), "r"(256u) : "memory");
    }
    __syncthreads();

    {
        const uint4* wg = (const uint4*)(Wsp + (size_t)blockIdx.y * 16384);
#pragma unroll
        for (int j = 0; j < 8; j++) {
            int fi = tid + j * 512;
            int plane = fi >> 11;
            int p = fi & 2047;
            int n = p >> 4;
            int c = p & 15;
            unsigned dst = shb + (((unsigned)plane * 8704u + (unsigned)n * 68u +
                                   (unsigned)c * 4u) << 2);
            cp16(dst, wg + fi);
        }
        asm volatile("cp.async.commit_group;" ::: "memory");
    }

    if (SCATTER && tid < 256) {
        const int* src = (tid < 128) ? u_idx : v_idx;
        sIdx[tid] = src[(size_t)blockIdx.y * n_rows + (tile << 7) + (tid & 127)];
    }
    __syncthreads();
    stage_bulk<SCATTER>(shb, 0, Ahi, Alo, sIdx + 128, tile << 7, tid, mb0);

    asm volatile("cp.async.wait_group 0;" ::: "memory");
    __syncthreads();

    const int hi4A = lane >> 4;
    const int hi4B = (lane & 8) >> 3;
    unsigned baseA[2];
#pragma unroll
    for (int rt = 0; rt < 2; rt++) {
        int rr = wr * 32 + rt * 16 + (lane & 15);
        baseA[rt] = shb + ((17408u + (unsigned)rr * 68u) << 2);
    }
    unsigned bBase[2][2];
#pragma unroll
    for (int nt2 = 0; nt2 < 2; nt2++) {
        int nn = wc * 32 + nt2 * 16 + (lane & 7) + ((lane & 16) >> 1);
#pragma unroll
        for (int pl = 0; pl < 2; pl++)
            bBase[nt2][pl] = shb + (((unsigned)pl * 8704u + (unsigned)nn * 68u) << 2);
    }

    int slot = 0;
    unsigned ph0 = 0, ph1 = 0;
#pragma unroll 1
    while (true) {
        const int row0 = tile << 7;
        const int next = tile + gridDim.x;
        const bool has_next = (next < n_tiles);

        int nreg = 0;
        if (SCATTER && has_next && tid < 256) {
            const int* src = (tid < 128) ? u_idx : v_idx;
            nreg = src[(size_t)blockIdx.y * n_rows + (next << 7) + (tid & 127)];
        }

        if (slot == 0) { mbar_wait(mb0, ph0); ph0 ^= 1; }
        else           { mbar_wait(mb1, ph1); ph1 ^= 1; }

        if (SCATTER && has_next && tid < 256)
            sIdx[(slot ^ 1) * 256 + tid] = nreg;
        __syncthreads();

        if (has_next)
            stage_bulk<SCATTER>(shb, slot ^ 1, Ahi, Alo, sIdx + (slot ^ 1) * 256 + 128,
                                next << 7, tid, slot ? mb0 : mb1);

        const unsigned slotb = (unsigned)slot * 69632u;
        float acc[2][4][4];
#pragma unroll
        for (int rt = 0; rt < 2; rt++)
#pragma unroll
            for (int nt = 0; nt < 4; nt++)
#pragma unroll
                for (int q = 0; q < 4; q++) acc[rt][nt][q] = 0.f;

#pragma unroll
        for (int ks = 0; ks < 8; ks++) {
            unsigned ah[2][4], al[2][4];
#pragma unroll
            for (int rt = 0; rt < 2; rt++) {
                unsigned ch = (unsigned)((2 * ks + hi4A) << 4);
                ldsm_x4(ah[rt][0], ah[rt][1], ah[rt][2], ah[rt][3],
                        baseA[rt] + slotb + ch);
                ldsm_x4(al[rt][0], al[rt][1], al[rt][2], al[rt][3],
                        baseA[rt] + slotb + 34816u + ch);
            }
#pragma unroll
            for (int nt2 = 0; nt2 < 2; nt2++) {
                unsigned bh[4], bl[4];
                unsigned ch = (unsigned)((2 * ks + hi4B) << 4);
                ldsm_x4(bh[0], bh[1], bh[2], bh[3], bBase[nt2][0] + ch);
                ldsm_x4(bl[0], bl[1], bl[2], bl[3], bBase[nt2][1] + ch);
#pragma unroll
                for (int half = 0; half < 2; half++) {
                    const int nt = nt2 * 2 + half;
                    unsigned b0h = bh[2 * half], b1h = bh[2 * half + 1];
                    unsigned b0l = bl[2 * half], b1l = bl[2 * half + 1];
#pragma unroll
                    for (int rt = 0; rt < 2; rt++) {
                        mma16816(acc[rt][nt], ah[rt][0], ah[rt][1], ah[rt][2], ah[rt][3], b0h, b1h);
                        mma16816(acc[rt][nt], ah[rt][0], ah[rt][1], ah[rt][2], ah[rt][3], b0l, b1l);
                        mma16816(acc[rt][nt], al[rt][0], al[rt][1], al[rt][2], al[rt][3], b0h, b1h);
                    }
                }
            }
        }

        const bool even = (tig & 1) == 0;
        const int colofs = (tig & 2) ? 4 : 0;
#pragma unroll
        for (int rt = 0; rt < 2; rt++) {
            const int arow = wr * 32 + rt * 16 + gid + (even ? 0 : 8);
            float* base;
            if (SCATTER) base = out + (size_t)sIdx[slot * 256 + arow] * CC;
            else         base = out + (size_t)(row0 + arow) * CC;
#pragma unroll
            for (int nt = 0; nt < 4; nt++) {
                float c0 = acc[rt][nt][0], c1 = acc[rt][nt][1];
                float c2 = acc[rt][nt][2], c3 = acc[rt][nt][3];
                float e0 = __shfl_xor_sync(0xffffffffu, c0, 1);
                float e1 = __shfl_xor_sync(0xffffffffu, c1, 1);
                float e2 = __shfl_xor_sync(0xffffffffu, c2, 1);
                float e3 = __shfl_xor_sync(0xffffffffu, c3, 1);
                float x0, x1, x2, x3;
                if (even) { x0 = c0; x1 = c1; x2 = e0; x3 = e1; }
                else      { x0 = e2; x1 = e3; x2 = c2; x3 = c3; }
                float* p = base + wc * 32 + nt * 8 + colofs;
                if (SCATTER) {
                    asm volatile("red.global.add.v4.f32 [%0], {%1,%2,%3,%4};"
                                 :: "l"(p), "f"(x0), "f"(x1), "f"(x2), "f"(x3) : "memory");
                } else {
                    float4 v; v.x = x0; v.y = x1; v.z = x2; v.w = x3;
                    *(float4*)p = v;
                }
            }
        }

        if (!has_next) break;
        if (SCATTER) __syncthreads();
        tile = next;
        slot ^= 1;
    }
}

// ---------------- fully fused: GN1+relu -> GEMM -> GN2 + residual + relu ----------------
// y = relu( GN2( relu(GN1(temp)) @ W ) + iden );  iden reconstructed from bf16 planes.
// Non-final blocks: write bf16 planes only. Final block: write f32 to outp only.
// smem (u32): same layout as round 13.
#define SMEM2_U32 53252
#define SMEM2_BYTES (SMEM2_U32 * 4)

__global__ void __launch_bounds__(512, 1)
norm_gemm_gn_res_kernel(const float* __restrict__ temp,
                        const unsigned* __restrict__ Wp,
                        const float* __restrict__ g1, const float* __restrict__ b1,
                        const float* __restrict__ g2, const float* __restrict__ b2,
                        const unsigned* __restrict__ ihi, const unsigned* __restrict__ ilo,
                        float* __restrict__ outp,          // non-null only on last block
                        unsigned* __restrict__ ohi, unsigned* __restrict__ olo,
                        int n_rows)
{
    extern __shared__ unsigned smem_u[];
    float* sGNS = (float*)(smem_u + 51712);
    float* sGNQ = (float*)(smem_u + 52224);
    float* sG1  = (float*)(smem_u + 52736);
    float* sB1  = (float*)(smem_u + 52864);
    float* sG2  = (float*)(smem_u + 52992);
    float* sB2  = (float*)(smem_u + 53120);

    const int tid  = threadIdx.x;
    const int lane = tid & 31;
    const int wid  = tid >> 5;
    const int wr   = wid & 3;
    const int wc   = wid >> 2;
    const int tig  = lane & 3;
    const int gid  = lane >> 2;

    const int n_tiles = n_rows >> 7;
    int tile = blockIdx.x;
    if (tile >= n_tiles) return;

    const unsigned shb = (unsigned)__cvta_generic_to_shared((void*)smem_u);
    const unsigned mb = shb + 53248u * 4u;
    const bool is_last = (outp != nullptr);

    if (tid == 0)
        asm volatile("mbarrier.init.shared.b64 [%0], %1;" :: "r"(mb), "r"(128u) : "memory");
    if (tid < 128)      sG1[tid]       = g1[tid];
    else if (tid < 256) sB1[tid - 128] = b1[tid - 128];
    else if (tid < 384) sG2[tid - 256] = g2[tid - 256];
    else                sB2[tid - 384] = b2[tid - 384];
    __syncthreads();

    // stage W
    {
        const uint4* wg = (const uint4*)Wp;
#pragma unroll
        for (int j = 0; j < 8; j++) {
            int fi = tid + j * 512;
            int plane = fi >> 11;
            int p = fi & 2047;
            int n = p >> 4;
            int c = p & 15;
            unsigned dst = shb + (((unsigned)plane * 8704u + (unsigned)n * 68u +
                                   (unsigned)c * 4u) << 2);
            cp16(dst, wg + fi);
        }
        asm volatile("cp.async.commit_group;" ::: "memory");
    }

    auto stage_f32 = [&](int row0) {
        if (tid < 128) {
            const void* srcp = temp + (size_t)(row0 + tid) * CC;
            unsigned dst = shb + ((17408u + (unsigned)tid * 132u) << 2);
            asm volatile("mbarrier.arrive.expect_tx.shared.b64 _, [%0], %1;"
                         :: "r"(mb), "r"(512u) : "memory");
            asm volatile(
                "cp.async.bulk.shared::cta.global.mbarrier::complete_tx::bytes [%0], [%1], %2, [%3];"
                :: "r"(dst), "l"(srcp), "r"(512u), "r"(mb) : "memory");
        }
    };
    stage_f32(tile << 7);
    asm volatile("cp.async.wait_group 0;" ::: "memory");   // W resident
    __syncthreads();

    const int hi4A = lane >> 4;
    const int hi4B = (lane & 8) >> 3;
    unsigned baseA[2];
#pragma unroll
    for (int rt = 0; rt < 2; rt++) {
        int rr = wr * 32 + rt * 16 + (lane & 15);
        baseA[rt] = shb + ((34304u + (unsigned)rr * 68u) << 2);
    }
    unsigned bBase[2][2];
#pragma unroll
    for (int nt2 = 0; nt2 < 2; nt2++) {
        int nn = wc * 32 + nt2 * 16 + (lane & 7) + ((lane & 16) >> 1);
#pragma unroll
        for (int pl = 0; pl < 2; pl++)
            bBase[nt2][pl] = shb + (((unsigned)pl * 8704u + (unsigned)nn * 68u) << 2);
    }
    const bool even = (tig & 1) == 0;
    const int colofs = (tig & 2) ? 4 : 0;
    const int erow0 = wr * 32 + gid + (even ? 0 : 8);

    const int cr  = tid >> 2;
    const int cs  = tid & 3;
    float* crow = (float*)(smem_u + 17408) + cr * 132 + cs * 32;
    unsigned* hrow = smem_u + 34304 + cr * 68 + cs * 16;
    unsigned* lrow = hrow + 8704;

    unsigned ph = 0;
#pragma unroll 1
    while (true) {
        const int row0 = tile << 7;
        const int next = tile + gridDim.x;
        const bool has_next = (next < n_tiles);

        mbar_wait(mb, ph); ph ^= 1;

        // ---- GN1 + relu + split -> bf16 planes (smem) ----
        {
            float y[32];
#pragma unroll
            for (int j = 0; j < 8; j++) {
                float4 v = *(const float4*)(crow + j * 4);
                y[4 * j] = v.x; y[4 * j + 1] = v.y; y[4 * j + 2] = v.z; y[4 * j + 3] = v.w;
            }
            float s = 0.f, q = 0.f;
#pragma unroll
            for (int j = 0; j < 32; j++) { s += y[j]; q += y[j] * y[j]; }
            s += __shfl_xor_sync(0xffffffffu, s, 1);
            q += __shfl_xor_sync(0xffffffffu, q, 1);
            s += __shfl_xor_sync(0xffffffffu, s, 2);
            q += __shfl_xor_sync(0xffffffffu, q, 2);
            float mu = s * (1.f / CC);
            float var = q * (1.f / CC) - mu * mu;
            float rs = rsqrtf(var + GN_EPS);
            const float* gg = sG1 + cs * 32;
            const float* bb = sB1 + cs * 32;
            unsigned hv[16], lv[16];
#pragma unroll
            for (int j = 0; j < 16; j++) {
                float h0 = fmaxf(fmaf((y[2 * j] - mu) * rs, gg[2 * j], bb[2 * j]), 0.f);
                float h1 = fmaxf(fmaf((y[2 * j + 1] - mu) * rs, gg[2 * j + 1], bb[2 * j + 1]), 0.f);
                split2(h0, h1, hv[j], lv[j]);
            }
#pragma unroll
            for (int j = 0; j < 4; j++) {
                *(uint4*)(hrow + j * 4) = *(uint4*)(hv + j * 4);
                *(uint4*)(lrow + j * 4) = *(uint4*)(lv + j * 4);
            }
        }
        __syncthreads();   // bf16 planes ready; f32 buffer free

        if (has_next) stage_f32(next << 7);

        // ---- MMA ----
        float acc[2][4][4];
#pragma unroll
        for (int rt = 0; rt < 2; rt++)
#pragma unroll
            for (int nt = 0; nt < 4; nt++)
#pragma unroll
                for (int q2 = 0; q2 < 4; q2++) acc[rt][nt][q2] = 0.f;

#pragma unroll
        for (int ks = 0; ks < 8; ks++) {
            unsigned ah[2][4], al[2][4];
#pragma unroll
            for (int rt = 0; rt < 2; rt++) {
                unsigned ch = (unsigned)((2 * ks + hi4A) << 4);
                ldsm_x4(ah[rt][0], ah[rt][1], ah[rt][2], ah[rt][3], baseA[rt] + ch);
                ldsm_x4(al[rt][0], al[rt][1], al[rt][2], al[rt][3], baseA[rt] + 34816u + ch);
            }
#pragma unroll
            for (int nt2 = 0; nt2 < 2; nt2++) {
                unsigned bh[4], bl[4];
                unsigned ch = (unsigned)((2 * ks + hi4B) << 4);
                ldsm_x4(bh[0], bh[1], bh[2], bh[3], bBase[nt2][0] + ch);
                ldsm_x4(bl[0], bl[1], bl[2], bl[3], bBase[nt2][1] + ch);
#pragma unroll
                for (int half = 0; half < 2; half++) {
                    const int nt = nt2 * 2 + half;
                    unsigned b0h = bh[2 * half], b1h = bh[2 * half + 1];
                    unsigned b0l = bl[2 * half], b1l = bl[2 * half + 1];
#pragma unroll
                    for (int rt = 0; rt < 2; rt++) {
                        mma16816(acc[rt][nt], ah[rt][0], ah[rt][1], ah[rt][2], ah[rt][3], b0h, b1h);
                        mma16816(acc[rt][nt], ah[rt][0], ah[rt][1], ah[rt][2], ah[rt][3], b0l, b1l);
                        mma16816(acc[rt][nt], al[rt][0], al[rt][1], al[rt][2], al[rt][3], b0h, b1h);
                    }
                }
            }
        }

        // ---- GN2 + residual + relu epilogue ----
        float sP[2] = {0.f, 0.f}, sQ[2] = {0.f, 0.f};
#pragma unroll
        for (int rt = 0; rt < 2; rt++) {
#pragma unroll
            for (int nt = 0; nt < 4; nt++) {
                float c0 = acc[rt][nt][0], c1 = acc[rt][nt][1];
                float c2 = acc[rt][nt][2], c3 = acc[rt][nt][3];
                float e0 = __shfl_xor_sync(0xffffffffu, c0, 1);
                float e1 = __shfl_xor_sync(0xffffffffu, c1, 1);
                float e2 = __shfl_xor_sync(0xffffffffu, c2, 1);
                float e3 = __shfl_xor_sync(0xffffffffu, c3, 1);
                float x0, x1, x2, x3;
                if (even) { x0 = c0; x1 = c1; x2 = e0; x3 = e1; }
                else      { x0 = e2; x1 = e3; x2 = c2; x3 = c3; }
                acc[rt][nt][0] = x0; acc[rt][nt][1] = x1;
                acc[rt][nt][2] = x2; acc[rt][nt][3] = x3;
                sP[rt] += x0 + x1 + x2 + x3;
                sQ[rt] += x0 * x0 + x1 * x1 + x2 * x2 + x3 * x3;
            }
            sP[rt] += __shfl_xor_sync(0xffffffffu, sP[rt], 2);
            sQ[rt] += __shfl_xor_sync(0xffffffffu, sQ[rt], 2);
        }
        if (tig < 2) {
            int rw = wr * 32 + gid + (tig & 1) * 8;
#pragma unroll
            for (int rt = 0; rt < 2; rt++) {
                sGNS[(rw + rt * 16) * 4 + wc] = sP[rt];
                sGNQ[(rw + rt * 16) * 4 + wc] = sQ[rt];
            }
        }
        __syncthreads();

#pragma unroll
        for (int rt = 0; rt < 2; rt++) {
            const int row = erow0 + rt * 16;
            float s4 = sGNS[row * 4] + sGNS[row * 4 + 1] + sGNS[row * 4 + 2] + sGNS[row * 4 + 3];
            float q4 = sGNQ[row * 4] + sGNQ[row * 4 + 1] + sGNQ[row * 4 + 2] + sGNQ[row * 4 + 3];
            float mu  = s4 * (1.f / CC);
            float var = q4 * (1.f / CC) - mu * mu;
            float rs  = rsqrtf(var + GN_EPS);
            const size_t grow = (size_t)(row0 + row);
            const unsigned* ihrow = ihi + grow * 64;
            const unsigned* ilrow = ilo + grow * 64;
#pragma unroll
            for (int nt = 0; nt < 4; nt++) {
                const int col0 = wc * 32 + nt * 8 + colofs;
                float4 gg = *(const float4*)(sG2 + col0);
                float4 bb = *(const float4*)(sB2 + col0);
                // reconstruct residual from bf16 planes (iden = hi + lo)
                uint2 ih2 = *(const uint2*)(ihrow + (col0 >> 1));
                uint2 il2 = *(const uint2*)(ilrow + (col0 >> 1));
                __nv_bfloat162 h0p = *reinterpret_cast<const __nv_bfloat162*>(&ih2.x);
                __nv_bfloat162 h1p = *reinterpret_cast<const __nv_bfloat162*>(&ih2.y);
                __nv_bfloat162 l0p = *reinterpret_cast<const __nv_bfloat162*>(&il2.x);
                __nv_bfloat162 l1p = *reinterpret_cast<const __nv_bfloat162*>(&il2.y);
                float id0 = __bfloat162float(h0p.x) + __bfloat162float(l0p.x);
                float id1 = __bfloat162float(h0p.y) + __bfloat162float(l0p.y);
                float id2 = __bfloat162float(h1p.x) + __bfloat162float(l1p.x);
                float id3 = __bfloat162float(h1p.y) + __bfloat162float(l1p.y);
                float y0 = fmaxf(fmaf((acc[rt][nt][0] - mu) * rs, gg.x, bb.x) + id0, 0.f);
                float y1 = fmaxf(fmaf((acc[rt][nt][1] - mu) * rs, gg.y, bb.y) + id1, 0.f);
                float y2 = fmaxf(fmaf((acc[rt][nt][2] - mu) * rs, gg.z, bb.z) + id2, 0.f);
                float y3 = fmaxf(fmaf((acc[rt][nt][3] - mu) * rs, gg.w, bb.w) + id3, 0.f);
                if (is_last) {
                    float4 o4; o4.x = y0; o4.y = y1; o4.z = y2; o4.w = y3;
                    *(float4*)(outp + grow * CC + col0) = o4;
                } else {
                    unsigned h0, l0, h1, l1;
                    split2(y0, y1, h0, l0);
                    split2(y2, y3, h1, l1);
                    uint2 hv; hv.x = h0; hv.y = h1;
                    uint2 lv; lv.x = l0; lv.y = l1;
                    *(uint2*)(ohi + grow * 64 + (col0 >> 1)) = hv;
                    *(uint2*)(olo + grow * 64 + (col0 >> 1)) = lv;
                }
            }
        }
        __syncthreads();   // GNS/GNQ + bf16 planes free for next tile

        if (!has_next) break;
        tile = next;
    }
}

// ---------------- input encoder -> bf16 planes only ----------------
__global__ void encoder_kernel(const float* __restrict__ ctrs, const float* __restrict__ feats,
                               const float* __restrict__ icw0, const float* __restrict__ icb0,
                               const float* __restrict__ icw1, const float* __restrict__ icg,
                               const float* __restrict__ icbt,
                               const float* __restrict__ ifw0, const float* __restrict__ ifb0,
                               const float* __restrict__ ifw1, const float* __restrict__ ifg,
                               const float* __restrict__ ifbt,
                               unsigned* __restrict__ ohi, unsigned* __restrict__ olo)
{
    const int tid = threadIdx.x;
    const int r = tid >> 7;
    const int c = tid & 127;
    const int row = (blockIdx.x << 1) + r;
    const int warp = (tid >> 5) & 3;
    const int lane = tid & 31;
    __shared__ float sh[2][CC];
    __shared__ float sred[2][2][4];

    float ysum = 0.f;
#pragma unroll
    for (int br = 0; br < 2; br++) {
        const float* x  = br ? feats : ctrs;
        const float* w0 = br ? ifw0 : icw0;
        const float* b0 = br ? ifb0 : icb0;
        const float* w1 = br ? ifw1 : icw1;
        const float* g  = br ? ifg  : icg;
        const float* bt = br ? ifbt : icbt;
        const float x0 = x[row * 2 + 0];
        const float x1 = x[row * 2 + 1];
        float h = fmaxf(fmaf(x1, w0[CC + c], fmaf(x0, w0[c], b0[c])), 0.f);
        __syncthreads();
        sh[r][c] = h;
        __syncthreads();
        float z = 0.f;
#pragma unroll 8
        for (int k = 0; k < CC; k++) z = fmaf(sh[r][k], w1[k * CC + c], z);
        float s = z, sq = z * z;
#pragma unroll
        for (int o = 16; o > 0; o >>= 1) {
            s  += __shfl_xor_sync(0xffffffffu, s, o);
            sq += __shfl_xor_sync(0xffffffffu, sq, o);
        }
        if (lane == 0) { sred[r][0][warp] = s; sred[r][1][warp] = sq; }
        __syncthreads();
        float mu  = (sred[r][0][0] + sred[r][0][1] + sred[r][0][2] + sred[r][0][3]) * (1.f / CC);
        float ms  = (sred[r][1][0] + sred[r][1][1] + sred[r][1][2] + sred[r][1][3]) * (1.f / CC);
        float var = ms - mu * mu;
        ysum += (z - mu) * rsqrtf(var + GN_EPS) * g[c] + bt[c];
    }
    float y = fmaxf(ysum, 0.f);
    float yn = __shfl_down_sync(0xffffffffu, y, 1);
    if ((c & 1) == 0) {
        unsigned h, l; split2(y, yn, h, l);
        ohi[(size_t)row * 64 + (c >> 1)] = h;
        olo[(size_t)row * 64 + (c >> 1)] = l;
    }
}

extern "C" void kernel_launch(void* const* d_in, const int* in_sizes, int n_in,
                              void* d_out, int out_size)
{
    const float* ctrs    = (const float*)d_in[0];
    const float* feats   = (const float*)d_in[1];
    const int*   pre_u   = (const int*)d_in[2];
    const int*   pre_v   = (const int*)d_in[3];
    const int*   suc_u   = (const int*)d_in[4];
    const int*   suc_v   = (const int*)d_in[5];
    const int*   left_u  = (const int*)d_in[6];
    const int*   left_v  = (const int*)d_in[7];
    const int*   right_u = (const int*)d_in[8];
    const int*   right_v = (const int*)d_in[9];
    const float* ic_w0   = (const float*)d_in[10];
    const float* ic_b0   = (const float*)d_in[11];
    const float* ic_w1   = (const float*)d_in[12];
    const float* ic_g    = (const float*)d_in[13];
    const float* ic_bt   = (const float*)d_in[14];
    const float* if_w0   = (const float*)d_in[15];
    const float* if_b0   = (const float*)d_in[16];
    const float* if_w1   = (const float*)d_in[17];
    const float* if_g    = (const float*)d_in[18];
    const float* if_bt   = (const float*)d_in[19];
    const float* ctr_w   = (const float*)d_in[20];
    const float* pre_w   = (const float*)d_in[21];
    const float* suc_w   = (const float*)d_in[22];
    const float* left_w  = (const float*)d_in[23];
    const float* right_w = (const float*)d_in[24];
    const float* norm_g  = (const float*)d_in[25];
    const float* norm_b  = (const float*)d_in[26];
    const float* ctr2_w  = (const float*)d_in[27];
    const float* ctr2_g  = (const float*)d_in[28];
    const float* ctr2_b  = (const float*)d_in[29];

    float* temp;
    unsigned *fhi, *flo, *wsp;
    cudaGetSymbolAddress((void**)&temp, g_temp);
    cudaGetSymbolAddress((void**)&fhi, g_fhi);
    cudaGetSymbolAddress((void**)&flo, g_flo);
    cudaGetSymbolAddress((void**)&wsp, g_wsp);

    cudaFuncSetAttribute(msg_mma_kernel<false>, cudaFuncAttributeMaxDynamicSharedMemorySize, SMEM_BYTES);
    cudaFuncSetAttribute(msg_mma_kernel<true>,  cudaFuncAttributeMaxDynamicSharedMemorySize, SMEM_BYTES);
    cudaFuncSetAttribute(norm_gemm_gn_res_kernel, cudaFuncAttributeMaxDynamicSharedMemorySize, SMEM2_BYTES);

    // one-time weight split (96 matrices)
    split_w_kernel<<<96, 256>>>(ctr_w, pre_w, suc_w, left_w, right_w, ctr2_w, wsp);

    // initial feat -> bf16 planes
    encoder_kernel<<<NN / 2, 256>>>(ctrs, feats,
                                    ic_w0, ic_b0, ic_w1, ic_g, ic_bt,
                                    if_w0, if_b0, if_w1, if_g, if_bt,
                                    fhi, flo);

    for (int i = 0; i < BB; i++) {
        // temp = feat @ ctr_w[i]
        msg_mma_kernel<false><<<dim3(148, 1), 512, SMEM_BYTES>>>(
            fhi, flo, wsp + (size_t)i * 16384, nullptr, nullptr, temp, NN);
        // scatter-add message passes
        msg_mma_kernel<true><<<dim3(74, SS), 512, SMEM_BYTES>>>(
            fhi, flo, wsp + (size_t)(6 + i * 6) * 16384, pre_u, pre_v, temp, EE);
        msg_mma_kernel<true><<<dim3(74, SS), 512, SMEM_BYTES>>>(
            fhi, flo, wsp + (size_t)(42 + i * 6) * 16384, suc_u, suc_v, temp, EE);
        msg_mma_kernel<true><<<dim3(148, 1), 512, SMEM_BYTES>>>(
            fhi, flo, wsp + (size_t)(78 + i) * 16384, left_u, left_v, temp, ELE);
        msg_mma_kernel<true><<<dim3(148, 1), 512, SMEM_BYTES>>>(
            fhi, flo, wsp + (size_t)(84 + i) * 16384, right_u, right_v, temp, ELE);
        // feat = relu(GN2(relu(GN1(temp)) @ ctr2_w[i]) + iden), iden from planes
        float* outp = (i == BB - 1) ? (float*)d_out : nullptr;
        norm_gemm_gn_res_kernel<<<148, 512, SMEM2_BYTES>>>(
            temp, wsp + (size_t)(90 + i) * 16384,
            norm_g + i * CC, norm_b + i * CC, ctr2_g + i * CC, ctr2_b + i * CC,
            fhi, flo, outp, fhi, flo, NN);
    }
}